// round 16
// baseline (speedup 1.0000x reference)
#include <cuda_runtime.h>
#include <cuda_fp16.h>
#include <math.h>
#include <stdint.h>

#define A_DIM 4608
#define L_DIM 4096
#define H_DIM 192
#define W_DIM 192
#define NTILE 36
#define NTILES_TOTAL (NTILE * NTILE)
#define BK    32
#define NIT   (L_DIM / BK)          // 128 k-chunks (all 3 passes fused per chunk)
#define TILE_B 8192                 // 128 rows x 64 B (swizzled, no pad)
#define STAGE (4 * TILE_B)          // Ahi | Alo | Bhi | Blo = 32768 B
#define NSTG  3
#define SMEM_BYTES (NSTG * STAGE)   // 98304
#define T_AHI 0
#define T_ALO TILE_B
#define T_BHI (2 * TILE_B)
#define T_BLO (3 * TILE_B)
#define NPERS 296

__device__ __half g_imgHi[(size_t)A_DIM * L_DIM];
__device__ __half g_imgLo[(size_t)A_DIM * L_DIM];
__device__ __half g_styHi[(size_t)A_DIM * L_DIM];
__device__ __half g_styLo[(size_t)A_DIM * L_DIM];
__device__ float g_invImg[A_DIM];
__device__ float g_invSty[A_DIM];
__device__ float g_np[2 * A_DIM * 8];
__device__ float g_pmax[NTILE * A_DIM];
__device__ int   g_pidx[NTILE * A_DIM];
__device__ unsigned int g_tileCtr;

__device__ __forceinline__ uint32_t smem_u32(const void* p) {
    uint32_t a;
    asm("{ .reg .u64 t; cvta.to.shared.u64 t, %1; cvt.u32.u64 %0, t; }" : "=r"(a) : "l"(p));
    return a;
}
#define CP16(dst, src) \
    asm volatile("cp.async.cg.shared.global [%0], [%1], 16;" :: "r"(dst), "l"(src) : "memory")
#define CP_COMMIT() asm volatile("cp.async.commit_group;" ::: "memory")
#define CP_WAIT1()  asm volatile("cp.async.wait_group 1;" ::: "memory")
#define CP_WAIT0()  asm volatile("cp.async.wait_group 0;" ::: "memory")
#define LDSM4(r0, r1, r2, r3, a) \
    asm volatile("ldmatrix.sync.aligned.m8n8.x4.shared.b16 {%0,%1,%2,%3}, [%4];" \
        : "=r"(r0), "=r"(r1), "=r"(r2), "=r"(r3) : "r"(a))
#define MMA_F16(c, a, b) \
    asm volatile("mma.sync.aligned.m16n8k16.row.col.f32.f16.f16.f32 " \
        "{%0,%1,%2,%3}, {%4,%5,%6,%7}, {%8,%9}, {%0,%1,%2,%3};" \
        : "+f"((c)[0]), "+f"((c)[1]), "+f"((c)[2]), "+f"((c)[3]) \
        : "r"((a)[0]), "r"((a)[1]), "r"((a)[2]), "r"((a)[3]), "r"((b)[0]), "r"((b)[1]))

// ---------------------------------------------------------------------------
// 1) unfold + fp16 hi/lo split + norm partials (block = (c, phc); 8 ph each)
// ---------------------------------------------------------------------------
__global__ void __launch_bounds__(192)
unfold_part(const float* __restrict__ in, int which) {
    __shared__ float sh[576];
    __shared__ float red[9][64];
    const int c = blockIdx.x, phc = blockIdx.y;
    const int tid = threadIdx.x;
    const float* src = in + (size_t)c * H_DIM * W_DIM;
    __half* outHi = which ? g_styHi : g_imgHi;
    __half* outLo = which ? g_styLo : g_imgLo;

    float acc0 = 0.0f, acc1 = 0.0f, acc2 = 0.0f;
    for (int pp = 0; pp < 8; ++pp) {
        const int ph = phc * 8 + pp;
        const float* rsrc = src + ph * 3 * W_DIM;
        sh[tid]       = rsrc[tid];
        sh[tid + 192] = rsrc[tid + 192];
        sh[tid + 384] = rsrc[tid + 384];
        __syncthreads();
        #pragma unroll
        for (int j = 0; j < 3; ++j) {
            int i = tid + j * 192;
            int seg = i >> 6, pw = i & 63;
            int kh = seg / 3, kw = seg - kh * 3;
            float v = sh[kh * W_DIM + pw * 3 + kw];
            __half hi = __float2half_rn(v);
            __half lo = __float2half_rn(v - __half2float(hi));
            size_t o = ((size_t)c * 9 + seg) * L_DIM + ph * 64 + pw;
            outHi[o] = hi;
            outLo[o] = lo;
            if (j == 0) acc0 = fmaf(v, v, acc0);
            else if (j == 1) acc1 = fmaf(v, v, acc1);
            else acc2 = fmaf(v, v, acc2);
        }
        __syncthreads();
    }
    red[(tid >> 6)][tid & 63]     = acc0;
    red[3 + (tid >> 6)][tid & 63] = acc1;
    red[6 + (tid >> 6)][tid & 63] = acc2;
    __syncthreads();
    if (tid < 9) {
        float s = 0.0f;
        #pragma unroll 8
        for (int k = 0; k < 64; ++k) s += red[tid][k];
        g_np[((size_t)which * A_DIM + c * 9 + tid) * 8 + phc] = s;
    }
}

// ---------------------------------------------------------------------------
// 2) norm finish + tile-counter reset
// ---------------------------------------------------------------------------
__global__ void norm_finish() {
    int i = blockIdx.x * blockDim.x + threadIdx.x;
    if (i == 0) g_tileCtr = 0;
    if (i >= 2 * A_DIM) return;
    float s = 0.0f;
    #pragma unroll
    for (int k = 0; k < 8; ++k) s += g_np[(size_t)i * 8 + k];
    float inv = 1.0f / sqrtf(s);
    if (i < A_DIM) g_invImg[i] = inv;
    else           g_invSty[i - A_DIM] = inv;
}

// ---------------------------------------------------------------------------
// 3) persistent fused fp16x3 GEMM: 128x128 tile, 4 warps (64x64 each), BK=32.
//    Per k-chunk, Ahi/Alo/Bhi/Blo loaded once; hi*hi + hi*lo + lo*hi all
//    computed from registers. 3-stage ring, swizzled 64B-pitch smem.
// ---------------------------------------------------------------------------
__global__ void __launch_bounds__(128, 2)
gemm_mma() {
    extern __shared__ char smem[];
    __shared__ int sh_tile;
    const uint32_t sb = smem_u32(smem);
    const int tid = threadIdx.x;
    const int wid = tid >> 5, lane = tid & 31;
    const int warp_m = wid & 1, warp_n = wid >> 1;
    const int m_base = warp_m * 64, n_base = warp_n * 64;

    // swizzle constants: physical seg = seg ^ ((row>>1)&3)
    const uint32_t swA = ((lane & 15) >> 1) & 3;
    const uint32_t swB = ((lane & 7) >> 1) & 3;
    const uint32_t aRow = (uint32_t)(m_base + (lane & 15)) * 64;
    const uint32_t bRow = (uint32_t)(n_base + ((lane >> 4) * 8) + (lane & 7)) * 64;

    for (;;) {
        if (tid == 0) sh_tile = (int)atomicAdd(&g_tileCtr, 1u);
        __syncthreads();
        const int tile = sh_tile;
        if (tile >= NTILES_TOTAL) break;
        const int bm = tile / NTILE, bn = tile - bm * NTILE;
        const int m0 = bm * 128, n0 = bn * 128;

        auto issue = [&](int chunk, int s) {
            const int kx = chunk * BK;
            const uint32_t st = sb + s * STAGE;
            #pragma unroll
            for (int u = 0; u < 16; ++u) {
                int idx = u * 128 + tid;
                int t4 = idx >> 9;               // which of the 4 tiles
                int r  = (idx >> 2) & 127;
                int sg = idx & 3;
                const __half* g;
                if (t4 == 0)      g = g_styHi + (size_t)(m0 + r) * L_DIM + kx + sg * 8;
                else if (t4 == 1) g = g_styLo + (size_t)(m0 + r) * L_DIM + kx + sg * 8;
                else if (t4 == 2) g = g_imgHi + (size_t)(n0 + r) * L_DIM + kx + sg * 8;
                else              g = g_imgLo + (size_t)(n0 + r) * L_DIM + kx + sg * 8;
                uint32_t dst = st + t4 * TILE_B + r * 64 + ((sg ^ ((r >> 1) & 3)) * 16);
                CP16(dst, g);
            }
            CP_COMMIT();
        };

        float acc[4][8][4];
        #pragma unroll
        for (int i = 0; i < 4; ++i)
            #pragma unroll
            for (int j = 0; j < 8; ++j)
                #pragma unroll
                for (int k = 0; k < 4; ++k) acc[i][j][k] = 0.0f;

        issue(0, 0);
        issue(1, 1);

        for (int it = 0; it < NIT; ++it) {
            const int s = it % NSTG;
            if (it + 2 < NIT) { CP_WAIT1(); } else { CP_WAIT0(); }
            __syncthreads();
            if (it + 2 < NIT) issue(it + 2, (it + 2) % NSTG);

            const uint32_t st = sb + s * STAGE;
            #pragma unroll
            for (int ks = 0; ks < 2; ++ks) {
                const uint32_t aSeg = ((uint32_t)(ks * 2 + (lane >> 4)) ^ swA) * 16;
                const uint32_t bSeg = ((uint32_t)(ks * 2 + ((lane >> 3) & 1)) ^ swB) * 16;
                const uint32_t aAd = st + aRow + aSeg;
                const uint32_t bAd = st + bRow + bSeg;

                uint32_t ah[4][4], bh[4][4], bl[4][4], al[4][4];
                #pragma unroll
                for (int mt = 0; mt < 4; ++mt)
                    LDSM4(ah[mt][0], ah[mt][1], ah[mt][2], ah[mt][3],
                          aAd + T_AHI + mt * 1024);
                #pragma unroll
                for (int np = 0; np < 4; ++np)
                    LDSM4(bh[np][0], bh[np][1], bh[np][2], bh[np][3],
                          bAd + T_BHI + np * 1024);
                #pragma unroll
                for (int mt = 0; mt < 4; ++mt)
                    #pragma unroll
                    for (int np = 0; np < 4; ++np) {
                        MMA_F16(acc[mt][np * 2],     ah[mt], (&bh[np][0]));
                        MMA_F16(acc[mt][np * 2 + 1], ah[mt], (&bh[np][2]));
                    }
                #pragma unroll
                for (int np = 0; np < 4; ++np)
                    LDSM4(bl[np][0], bl[np][1], bl[np][2], bl[np][3],
                          bAd + T_BLO + np * 1024);
                #pragma unroll
                for (int mt = 0; mt < 4; ++mt)
                    #pragma unroll
                    for (int np = 0; np < 4; ++np) {
                        MMA_F16(acc[mt][np * 2],     ah[mt], (&bl[np][0]));
                        MMA_F16(acc[mt][np * 2 + 1], ah[mt], (&bl[np][2]));
                    }
                #pragma unroll
                for (int mt = 0; mt < 4; ++mt)
                    LDSM4(al[mt][0], al[mt][1], al[mt][2], al[mt][3],
                          aAd + T_ALO + mt * 1024);
                #pragma unroll
                for (int mt = 0; mt < 4; ++mt)
                    #pragma unroll
                    for (int np = 0; np < 4; ++np) {
                        MMA_F16(acc[mt][np * 2],     al[mt], (&bh[np][0]));
                        MMA_F16(acc[mt][np * 2 + 1], al[mt], (&bh[np][2]));
                    }
            }
            __syncthreads();
        }

        // ---- register epilogue: column max of acc * g_invImg[row] ----
        float invR[8];
        #pragma unroll
        for (int mt = 0; mt < 4; ++mt)
            #pragma unroll
            for (int h = 0; h < 2; ++h)
                invR[mt * 2 + h] = g_invImg[m0 + m_base + mt * 16 + h * 8 + (lane >> 2)];

        float* pv = (float*)smem;
        int*   pi = (int*)(smem + 2 * 128 * 4);

        #pragma unroll
        for (int j = 0; j < 8; ++j)
            #pragma unroll
            for (int p = 0; p < 2; ++p) {
                float bv = -3.402823466e38f;
                int bi = 0x7fffffff;
                #pragma unroll
                for (int mt = 0; mt < 4; ++mt)
                    #pragma unroll
                    for (int h = 0; h < 2; ++h) {
                        float v = acc[mt][j][h * 2 + p] * invR[mt * 2 + h];
                        int row = m0 + m_base + mt * 16 + h * 8 + (lane >> 2);
                        if (v > bv || (v == bv && row < bi)) { bv = v; bi = row; }
                    }
                #pragma unroll
                for (int o = 4; o < 32; o <<= 1) {
                    float ov = __shfl_xor_sync(0xffffffffu, bv, o);
                    int   oi = __shfl_xor_sync(0xffffffffu, bi, o);
                    if (ov > bv || (ov == bv && oi < bi)) { bv = ov; bi = oi; }
                }
                if ((lane >> 2) == 0) {
                    int col = n_base + j * 8 + (lane & 3) * 2 + p;
                    pv[warp_m * 128 + col] = bv;
                    pi[warp_m * 128 + col] = bi;
                }
            }
        __syncthreads();

        if (tid < 128) {
            float bv = pv[tid];
            int bi = pi[tid];
            float v = pv[128 + tid];
            int  i2 = pi[128 + tid];
            if (v > bv || (v == bv && i2 < bi)) { bv = v; bi = i2; }
            g_pmax[bm * A_DIM + n0 + tid] = bv;
            g_pidx[bm * A_DIM + n0 + tid] = bi;
        }
        __syncthreads();
    }
}

// ---------------------------------------------------------------------------
// 4) final reduce
// ---------------------------------------------------------------------------
__global__ void final_kernel(float* __restrict__ out) {
    int j = blockIdx.x * blockDim.x + threadIdx.x;
    if (j >= A_DIM) return;
    float bv = g_pmax[j];
    int bi = g_pidx[j];
    #pragma unroll
    for (int t = 1; t < NTILE; ++t) {
        float v = g_pmax[t * A_DIM + j];
        int i = g_pidx[t * A_DIM + j];
        if (v > bv || (v == bv && i < bi)) { bv = v; bi = i; }
    }
    out[j]         = (float)bi;
    out[A_DIM + j] = bv * g_invSty[j];
}

// ---------------------------------------------------------------------------
extern "C" void kernel_launch(void* const* d_in, const int* in_sizes, int n_in,
                              void* d_out, int out_size) {
    const float* model = (const float*)d_in[0];
    const float* style = (const float*)d_in[1];
    float* out = (float*)d_out;

    cudaFuncSetAttribute(gemm_mma, cudaFuncAttributeMaxDynamicSharedMemorySize, SMEM_BYTES);

    unfold_part<<<dim3(512, 8), 192>>>(model, 0);
    unfold_part<<<dim3(512, 8), 192>>>(style, 1);
    norm_finish<<<36, 256>>>();
    gemm_mma<<<NPERS, 128, SMEM_BYTES>>>();
    final_kernel<<<A_DIM / 256, 256>>>(out);
}

// round 17
// speedup vs baseline: 1.1982x; 1.1982x over previous
#include <cuda_runtime.h>
#include <cuda_fp16.h>
#include <math.h>
#include <stdint.h>

#define A_DIM 4608
#define L_DIM 4096
#define H_DIM 192
#define W_DIM 192
#define NTILE 36
#define NTILES_TOTAL (NTILE * NTILE)
#define BK    32
#define NIT   (L_DIM / BK)          // 128 fused k-chunks
#define PITCH 80
#define TILE_B (128 * PITCH)        // 10240 B
#define STAGE (4 * TILE_B)          // Ahi | Alo | Bhi | Blo = 40960 B
#define NSTG  2
#define SMEM_BYTES (NSTG * STAGE)   // 81920
#define T_AHI 0
#define T_ALO TILE_B
#define T_BHI (2 * TILE_B)
#define T_BLO (3 * TILE_B)
#define NPERS 296

__device__ __half g_imgHi[(size_t)A_DIM * L_DIM];
__device__ __half g_imgLo[(size_t)A_DIM * L_DIM];
__device__ __half g_styHi[(size_t)A_DIM * L_DIM];
__device__ __half g_styLo[(size_t)A_DIM * L_DIM];
__device__ float g_invImg[A_DIM];
__device__ float g_invSty[A_DIM];
__device__ float g_np[2 * A_DIM * 8];
__device__ float g_pmax[NTILE * A_DIM];
__device__ int   g_pidx[NTILE * A_DIM];
__device__ unsigned int g_tileCtr;

__device__ __forceinline__ uint32_t smem_u32(const void* p) {
    uint32_t a;
    asm("{ .reg .u64 t; cvta.to.shared.u64 t, %1; cvt.u32.u64 %0, t; }" : "=r"(a) : "l"(p));
    return a;
}
#define CP16(dst, src) \
    asm volatile("cp.async.cg.shared.global [%0], [%1], 16;" :: "r"(dst), "l"(src) : "memory")
#define CP_COMMIT() asm volatile("cp.async.commit_group;" ::: "memory")
#define CP_WAIT1()  asm volatile("cp.async.wait_group 1;" ::: "memory")
#define CP_WAIT0()  asm volatile("cp.async.wait_group 0;" ::: "memory")
#define LDSM4(r0, r1, r2, r3, a) \
    asm volatile("ldmatrix.sync.aligned.m8n8.x4.shared.b16 {%0,%1,%2,%3}, [%4];" \
        : "=r"(r0), "=r"(r1), "=r"(r2), "=r"(r3) : "r"(a))
#define MMA_F16(c, a, b) \
    asm volatile("mma.sync.aligned.m16n8k16.row.col.f32.f16.f16.f32 " \
        "{%0,%1,%2,%3}, {%4,%5,%6,%7}, {%8,%9}, {%0,%1,%2,%3};" \
        : "+f"((c)[0]), "+f"((c)[1]), "+f"((c)[2]), "+f"((c)[3]) \
        : "r"((a)[0]), "r"((a)[1]), "r"((a)[2]), "r"((a)[3]), "r"((b)[0]), "r"((b)[1]))

// ---------------------------------------------------------------------------
// 1) unfold + fp16 hi/lo split + norm partials (block = (c, phc); 8 ph each)
// ---------------------------------------------------------------------------
__global__ void __launch_bounds__(192)
unfold_part(const float* __restrict__ in, int which) {
    __shared__ float sh[576];
    __shared__ float red[9][64];
    const int c = blockIdx.x, phc = blockIdx.y;
    const int tid = threadIdx.x;
    const float* src = in + (size_t)c * H_DIM * W_DIM;
    __half* outHi = which ? g_styHi : g_imgHi;
    __half* outLo = which ? g_styLo : g_imgLo;

    float acc0 = 0.0f, acc1 = 0.0f, acc2 = 0.0f;
    for (int pp = 0; pp < 8; ++pp) {
        const int ph = phc * 8 + pp;
        const float* rsrc = src + ph * 3 * W_DIM;
        sh[tid]       = rsrc[tid];
        sh[tid + 192] = rsrc[tid + 192];
        sh[tid + 384] = rsrc[tid + 384];
        __syncthreads();
        #pragma unroll
        for (int j = 0; j < 3; ++j) {
            int i = tid + j * 192;
            int seg = i >> 6, pw = i & 63;
            int kh = seg / 3, kw = seg - kh * 3;
            float v = sh[kh * W_DIM + pw * 3 + kw];
            __half hi = __float2half_rn(v);
            __half lo = __float2half_rn(v - __half2float(hi));
            size_t o = ((size_t)c * 9 + seg) * L_DIM + ph * 64 + pw;
            outHi[o] = hi;
            outLo[o] = lo;
            if (j == 0) acc0 = fmaf(v, v, acc0);
            else if (j == 1) acc1 = fmaf(v, v, acc1);
            else acc2 = fmaf(v, v, acc2);
        }
        __syncthreads();
    }
    red[(tid >> 6)][tid & 63]     = acc0;
    red[3 + (tid >> 6)][tid & 63] = acc1;
    red[6 + (tid >> 6)][tid & 63] = acc2;
    __syncthreads();
    if (tid < 9) {
        float s = 0.0f;
        #pragma unroll 8
        for (int k = 0; k < 64; ++k) s += red[tid][k];
        g_np[((size_t)which * A_DIM + c * 9 + tid) * 8 + phc] = s;
    }
}

// ---------------------------------------------------------------------------
// 2) norm finish + tile-counter reset
// ---------------------------------------------------------------------------
__global__ void norm_finish() {
    int i = blockIdx.x * blockDim.x + threadIdx.x;
    if (i == 0) g_tileCtr = 0;
    if (i >= 2 * A_DIM) return;
    float s = 0.0f;
    #pragma unroll
    for (int k = 0; k < 8; ++k) s += g_np[(size_t)i * 8 + k];
    float inv = 1.0f / sqrtf(s);
    if (i < A_DIM) g_invImg[i] = inv;
    else           g_invSty[i - A_DIM] = inv;
}

// ---------------------------------------------------------------------------
// 3) persistent fused fp16x3 GEMM: 128x128 tile, 4 warps (64x64 each), BK=32.
//    Per chunk: load Ahi/Alo/Bhi/Blo once (PITCH-80, conflict-free), compute
//    hi*hi + hi*lo + lo*hi from registers. 2-stage double buffer.
// ---------------------------------------------------------------------------
__global__ void __launch_bounds__(128, 2)
gemm_mma() {
    extern __shared__ char smem[];
    __shared__ int sh_tile;
    const uint32_t sb = smem_u32(smem);
    const int tid = threadIdx.x;
    const int wid = tid >> 5, lane = tid & 31;
    const int warp_m = wid & 1, warp_n = wid >> 1;
    const int m_base = warp_m * 64, n_base = warp_n * 64;

    const uint32_t aOff = (uint32_t)(m_base + (lane & 15)) * PITCH + (lane >> 4) * 16;
    const uint32_t bOff = (uint32_t)(n_base + ((lane >> 4) * 8) + (lane & 7)) * PITCH
                        + (((lane >> 3) & 1) * 16);

    for (;;) {
        if (tid == 0) sh_tile = (int)atomicAdd(&g_tileCtr, 1u);
        __syncthreads();
        const int tile = sh_tile;
        if (tile >= NTILES_TOTAL) break;
        const int bm = tile / NTILE, bn = tile - bm * NTILE;
        const int m0 = bm * 128, n0 = bn * 128;

        auto issue = [&](int chunk, int s) {
            const int kx = chunk * BK;
            const uint32_t st = sb + s * STAGE;
            // 4 tiles x 128 rows x 4 segs = 2048 chunks / 128 threads = 16 each
            #pragma unroll
            for (int u = 0; u < 16; ++u) {
                int idx = u * 128 + tid;
                int t4 = idx >> 9;
                int r  = (idx >> 2) & 127;
                int sg = idx & 3;
                const __half* g;
                if (t4 == 0)      g = g_styHi + (size_t)(m0 + r) * L_DIM + kx + sg * 8;
                else if (t4 == 1) g = g_styLo + (size_t)(m0 + r) * L_DIM + kx + sg * 8;
                else if (t4 == 2) g = g_imgHi + (size_t)(n0 + r) * L_DIM + kx + sg * 8;
                else              g = g_imgLo + (size_t)(n0 + r) * L_DIM + kx + sg * 8;
                CP16(st + t4 * TILE_B + r * PITCH + sg * 16, g);
            }
            CP_COMMIT();
        };

        float acc[4][8][4];
        #pragma unroll
        for (int i = 0; i < 4; ++i)
            #pragma unroll
            for (int j = 0; j < 8; ++j)
                #pragma unroll
                for (int k = 0; k < 4; ++k) acc[i][j][k] = 0.0f;

        issue(0, 0);

        for (int it = 0; it < NIT; ++it) {
            const int s = it & 1;
            if (it + 1 < NIT) { issue(it + 1, s ^ 1); CP_WAIT1(); }
            else              { CP_WAIT0(); }
            __syncthreads();

            const uint32_t st = sb + s * STAGE;
            #pragma unroll
            for (int ks = 0; ks < 2; ++ks) {
                const uint32_t aAd = st + aOff + ks * 32;
                const uint32_t bAd = st + bOff + ks * 32;
                uint32_t ah[4][4], bh[4][4], bl[4][4], al[4][4];
                #pragma unroll
                for (int mt = 0; mt < 4; ++mt)
                    LDSM4(ah[mt][0], ah[mt][1], ah[mt][2], ah[mt][3],
                          aAd + T_AHI + mt * 16 * PITCH);
                #pragma unroll
                for (int np = 0; np < 4; ++np)
                    LDSM4(bh[np][0], bh[np][1], bh[np][2], bh[np][3],
                          bAd + T_BHI + np * 16 * PITCH);
                #pragma unroll
                for (int mt = 0; mt < 4; ++mt)
                    #pragma unroll
                    for (int np = 0; np < 4; ++np) {
                        MMA_F16(acc[mt][np * 2],     ah[mt], (&bh[np][0]));
                        MMA_F16(acc[mt][np * 2 + 1], ah[mt], (&bh[np][2]));
                    }
                #pragma unroll
                for (int np = 0; np < 4; ++np)
                    LDSM4(bl[np][0], bl[np][1], bl[np][2], bl[np][3],
                          bAd + T_BLO + np * 16 * PITCH);
                #pragma unroll
                for (int mt = 0; mt < 4; ++mt)
                    #pragma unroll
                    for (int np = 0; np < 4; ++np) {
                        MMA_F16(acc[mt][np * 2],     ah[mt], (&bl[np][0]));
                        MMA_F16(acc[mt][np * 2 + 1], ah[mt], (&bl[np][2]));
                    }
                #pragma unroll
                for (int mt = 0; mt < 4; ++mt)
                    LDSM4(al[mt][0], al[mt][1], al[mt][2], al[mt][3],
                          aAd + T_ALO + mt * 16 * PITCH);
                #pragma unroll
                for (int mt = 0; mt < 4; ++mt)
                    #pragma unroll
                    for (int np = 0; np < 4; ++np) {
                        MMA_F16(acc[mt][np * 2],     al[mt], (&bh[np][0]));
                        MMA_F16(acc[mt][np * 2 + 1], al[mt], (&bh[np][2]));
                    }
            }
            __syncthreads();
        }

        // ---- register epilogue: column max of acc * g_invImg[row] ----
        float invR[8];
        #pragma unroll
        for (int mt = 0; mt < 4; ++mt)
            #pragma unroll
            for (int h = 0; h < 2; ++h)
                invR[mt * 2 + h] = g_invImg[m0 + m_base + mt * 16 + h * 8 + (lane >> 2)];

        float* pv = (float*)smem;
        int*   pi = (int*)(smem + 2 * 128 * 4);

        #pragma unroll
        for (int j = 0; j < 8; ++j)
            #pragma unroll
            for (int p = 0; p < 2; ++p) {
                float bv = -3.402823466e38f;
                int bi = 0x7fffffff;
                #pragma unroll
                for (int mt = 0; mt < 4; ++mt)
                    #pragma unroll
                    for (int h = 0; h < 2; ++h) {
                        float v = acc[mt][j][h * 2 + p] * invR[mt * 2 + h];
                        int row = m0 + m_base + mt * 16 + h * 8 + (lane >> 2);
                        if (v > bv || (v == bv && row < bi)) { bv = v; bi = row; }
                    }
                #pragma unroll
                for (int o = 4; o < 32; o <<= 1) {
                    float ov = __shfl_xor_sync(0xffffffffu, bv, o);
                    int   oi = __shfl_xor_sync(0xffffffffu, bi, o);
                    if (ov > bv || (ov == bv && oi < bi)) { bv = ov; bi = oi; }
                }
                if ((lane >> 2) == 0) {
                    int col = n_base + j * 8 + (lane & 3) * 2 + p;
                    pv[warp_m * 128 + col] = bv;
                    pi[warp_m * 128 + col] = bi;
                }
            }
        __syncthreads();

        if (tid < 128) {
            float bv = pv[tid];
            int bi = pi[tid];
            float v = pv[128 + tid];
            int  i2 = pi[128 + tid];
            if (v > bv || (v == bv && i2 < bi)) { bv = v; bi = i2; }
            g_pmax[bm * A_DIM + n0 + tid] = bv;
            g_pidx[bm * A_DIM + n0 + tid] = bi;
        }
        __syncthreads();
    }
}

// ---------------------------------------------------------------------------
// 4) final reduce
// ---------------------------------------------------------------------------
__global__ void final_kernel(float* __restrict__ out) {
    int j = blockIdx.x * blockDim.x + threadIdx.x;
    if (j >= A_DIM) return;
    float bv = g_pmax[j];
    int bi = g_pidx[j];
    #pragma unroll
    for (int t = 1; t < NTILE; ++t) {
        float v = g_pmax[t * A_DIM + j];
        int i = g_pidx[t * A_DIM + j];
        if (v > bv || (v == bv && i < bi)) { bv = v; bi = i; }
    }
    out[j]         = (float)bi;
    out[A_DIM + j] = bv * g_invSty[j];
}

// ---------------------------------------------------------------------------
extern "C" void kernel_launch(void* const* d_in, const int* in_sizes, int n_in,
                              void* d_out, int out_size) {
    const float* model = (const float*)d_in[0];
    const float* style = (const float*)d_in[1];
    float* out = (float*)d_out;

    cudaFuncSetAttribute(gemm_mma, cudaFuncAttributeMaxDynamicSharedMemorySize, SMEM_BYTES);

    unfold_part<<<dim3(512, 8), 192>>>(model, 0);
    unfold_part<<<dim3(512, 8), 192>>>(style, 1);
    norm_finish<<<36, 256>>>();
    gemm_mma<<<NPERS, 128, SMEM_BYTES>>>();
    final_kernel<<<A_DIM / 256, 256>>>(out);
}